// round 16
// baseline (speedup 1.0000x reference)
#include <cuda_runtime.h>
#include <math.h>

#define N_NODES 100000
#define N_EDGES 1000000
#define D_NODE 64
#define D_EDGE 16
#define NUM_PAR 80
#define HIDDEN 160

#define NBLOCKS 592               // 148 SMs x 4 blocks, all co-resident
#define NTHREADS 256              // 8 warps
#define CHUNK_E 256               // edges per chunk (1 per thread)
#define NCHUNKS ((N_EDGES + CHUNK_E - 1) / CHUNK_E)   // 3907
#define ROUNDS 4                  // claim rounds per block
#define CPR 2                     // chunks per round (1 atomic claims 2)
#define MAXC (ROUNDS * CPR)       // 8: max chunks a block can own (592*8=4736 >= 3907)

// Scratch (allocation-free rule).
__device__ float g_p[N_NODES];
__device__ int   g_cnt;           // barrier arrivals (self-resetting)
__device__ int   g_tick;          // work-stealing ticket (self-resetting)
__device__ volatile int g_flag;   // barrier generation (monotone across replays)

// Warp-cooperative collapsed weight for one row r of W1:
//   w[r] = sum_j W1[r,j] * W2[j], lane-parallel over j (5 strides of 32).
__device__ __forceinline__ float collapse_row(const float* __restrict__ W1,
                                              const float* __restrict__ w2reg,
                                              int r, int lane) {
    const float* row = W1 + r * HIDDEN;
    float s = 0.f;
    #pragma unroll
    for (int k = 0; k < 5; k++)
        s = fmaf(__ldg(row + lane + 32 * k), w2reg[k], s);
    #pragma unroll
    for (int o = 16; o > 0; o >>= 1)
        s += __shfl_xor_sync(0xFFFFFFFFu, s, o);
    return s;   // valid in all lanes
}

// ---------------------------------------------------------------------------
// Fused persistent kernel (4 blocks/SM). R10 structure + dynamic stealing:
//   Stage 0: per-block weight collapse (W1/W2 L2-resident after wave 1).
//   Stage 1: node projections p[n] = x[n].w[0:64] (static partition).
//   Stage 2 (pre-barrier): ea chunks claimed DYNAMICALLY from a global
//     ticket (2 chunks per atomic, 4 rounds). Fast blocks claim more valid
//     chunks; slow blocks' late claims fall past NCHUNKS and no-op. This
//     equalizes barrier-arrival times (multi-CTA spread is up to ~2x).
//     Per chunk: indices (coalesced low-word loads; int32/int64 via mult)
//     and q = ea.w[64:80] + c.
//   Barrier: sense-reversing grid barrier; last arriver resets ticket.
//   Stage 3: scattered p-gathers for the SAME claimed chunks, sigmoid, store.
// ---------------------------------------------------------------------------
__global__ __launch_bounds__(NTHREADS, 4)
void fused_kernel(const float* __restrict__ x,
                  const void*  __restrict__ ei_raw,
                  const float* __restrict__ ea,
                  const float* __restrict__ W1,
                  const float* __restrict__ b1,
                  const float* __restrict__ W2,
                  const float* __restrict__ b2,
                  float* __restrict__ out) {
    __shared__ float sw[NUM_PAR];
    __shared__ float sc;
    __shared__ int   smult;
    __shared__ int   s_cid;
    int t = threadIdx.x;
    int warp = t >> 5;
    int lane = t & 31;

    // ---- Stage 0: weight collapse (all 8 warps; 10 rows each) ----
    {
        float w2[5];
        #pragma unroll
        for (int k = 0; k < 5; k++) w2[k] = __ldg(W2 + lane + 32 * k);
        #pragma unroll
        for (int rr = 0; rr < 10; rr++) {
            int r = warp * 10 + rr;
            float s = collapse_row(W1, w2, r, lane);
            if (lane == 0) sw[r] = s;
        }
        if (warp == 7) {   // c = b1 . W2 + b2
            float s = 0.f;
            #pragma unroll
            for (int k = 0; k < 5; k++)
                s = fmaf(__ldg(b1 + lane + 32 * k), w2[k], s);
            #pragma unroll
            for (int o = 16; o > 0; o >>= 1)
                s += __shfl_xor_sync(0xFFFFFFFFu, s, o);
            if (lane == 0) sc = s + __ldg(b2);
        }
        if (warp == 0) {
            // Dtype probe: 32 entries as int64 all in [0,N_NODES) <=> int64
            // (int32 data would need 32 zero hi-words: P ~ 1e-160).
            const long long* ei64 = (const long long*)ei_raw;
            long long v = __ldg(ei64 + lane);
            unsigned b = __ballot_sync(0xFFFFFFFFu, v >= 0 && v < N_NODES);
            if (lane == 0) smult = (b == 0xFFFFFFFFu) ? 2 : 1;
        }
    }
    __syncthreads();

    // ---- Stage 1: node projections (2 nodes/warp/iter; as in R10) ----
    {
        int half = lane >> 4;
        int q    = lane & 15;
        float w0 = sw[q * 4 + 0];
        float w1 = sw[q * 4 + 1];
        float w2r = sw[q * 4 + 2];
        float w3 = sw[q * 4 + 3];

        const float4* x4 = (const float4*)x;
        const int stride = NBLOCKS * 16;

        for (int node = blockIdx.x * 16 + warp * 2 + half;
             node < N_NODES; node += stride) {
            float4 v = __ldg(x4 + (size_t)node * 16 + q);
            float s = fmaf(v.x, w0, fmaf(v.y, w1, fmaf(v.z, w2r, v.w * w3)));
            #pragma unroll
            for (int o = 8; o > 0; o >>= 1)
                s += __shfl_xor_sync(0xFFFFFFFFu, s, o);
            if (q == 0) g_p[node] = s;
        }
    }

    // ---- Stage 2 (pre-barrier): dynamically claimed ea chunks ----
    const int mult = smult;
    const float cc = sc;
    const int* eidx = (const int*)ei_raw;   // low 4B hold the value (LE)

    int   rc[ROUNDS];                        // first cid of each round
    int   srcs[MAXC], dsts[MAXC];
    float q[MAXC];

    #pragma unroll
    for (int r = 0; r < ROUNDS; r++) {
        __syncthreads();                     // prior round done reading s_cid
        if (t == 0) s_cid = atomicAdd(&g_tick, CPR);
        __syncthreads();
        int cid0 = s_cid;
        rc[r] = cid0;

        #pragma unroll
        for (int j = 0; j < CPR; j++) {
            int it  = r * CPR + j;
            int cid = cid0 + j;
            srcs[it] = 0; dsts[it] = 0; q[it] = 0.f;
            if (cid < NCHUNKS) {
                int e  = cid * CHUNK_E + t;
                int ec = e < N_EDGES ? e : (N_EDGES - 1);
                srcs[it] = __ldg(eidx + (size_t)mult * ec);
                dsts[it] = __ldg(eidx + (size_t)mult * ((size_t)N_EDGES + ec));

                const float4* A = (const float4*)(ea + (size_t)ec * D_EDGE);
                float4 a0 = __ldg(A + 0);
                float4 a1 = __ldg(A + 1);
                float4 a2 = __ldg(A + 2);
                float4 a3 = __ldg(A + 3);
                float z0 = fmaf(a0.x, sw[64], fmaf(a0.y, sw[65], fmaf(a0.z, sw[66], a0.w * sw[67])));
                float z1 = fmaf(a1.x, sw[68], fmaf(a1.y, sw[69], fmaf(a1.z, sw[70], a1.w * sw[71])));
                float z2 = fmaf(a2.x, sw[72], fmaf(a2.y, sw[73], fmaf(a2.z, sw[74], a2.w * sw[75])));
                float z3 = fmaf(a3.x, sw[76], fmaf(a3.y, sw[77], fmaf(a3.z, sw[78], a3.w * sw[79])));
                q[it] = cc + ((z0 + z1) + (z2 + z3));
            }
        }
    }

    // ---- Grid barrier (sense-reversing; all blocks resident) ----
    __syncthreads();
    if (t == 0) {
        int gen = g_flag;
        __threadfence();                     // p writes + claims visible
        int a = atomicAdd(&g_cnt, 1);
        if (a == NBLOCKS - 1) {
            g_cnt  = 0;                      // self-reset for next replay
            g_tick = 0;
            __threadfence();
            g_flag = gen + 1;                // release
        } else {
            while (g_flag == gen) { }        // spin (volatile)
        }
        __threadfence();
    }
    __syncthreads();

    // ---- Stage 3: scattered gathers + finish (same claimed chunks) ----
    float ps[MAXC];
    #pragma unroll
    for (int it = 0; it < MAXC; it++)
        ps[it] = g_p[srcs[it]] + g_p[dsts[it]];

    #pragma unroll
    for (int r = 0; r < ROUNDS; r++) {
        #pragma unroll
        for (int j = 0; j < CPR; j++) {
            int it  = r * CPR + j;
            int cid = rc[r] + j;
            if (cid < NCHUNKS) {
                int e = cid * CHUNK_E + t;
                if (e < N_EDGES) {
                    float z = ps[it] + q[it];
                    out[e] = 1.0f / (1.0f + __expf(-z));
                }
            }
        }
    }
}

extern "C" void kernel_launch(void* const* d_in, const int* in_sizes, int n_in,
                              void* d_out, int out_size) {
    // metadata order: x, edge_index, edge_attr, W1, b1, W2, b2
    const float* x  = (const float*)d_in[0];
    const void*  ei = d_in[1];
    const float* ea = (const float*)d_in[2];
    const float* W1 = (const float*)d_in[3];
    const float* b1 = (const float*)d_in[4];
    const float* W2 = (const float*)d_in[5];
    const float* b2 = (const float*)d_in[6];
    float* out = (float*)d_out;

    fused_kernel<<<NBLOCKS, NTHREADS>>>(x, ei, ea, W1, b1, W2, b2, out);
}

// round 17
// speedup vs baseline: 1.2222x; 1.2222x over previous
#include <cuda_runtime.h>
#include <math.h>

#define N_NODES 100000
#define N_EDGES 1000000
#define D_NODE 64
#define D_EDGE 16
#define NUM_PAR 80
#define HIDDEN 160

#define NBLOCKS 592               // 148 SMs x 4 blocks, all co-resident
#define NTHREADS 256              // 8 warps
#define EPT 7                     // edges per thread: 592*256*7 = 1,060,864 >= 1e6

// Scratch (allocation-free rule).
__device__ float g_p[N_NODES];
__device__ int   g_cnt;           // barrier arrivals (self-resetting)
__device__ volatile int g_flag;   // barrier generation (monotone across replays)

// Warp-cooperative collapsed weight for one row r of W1:
//   w[r] = sum_j W1[r,j] * W2[j], lane-parallel over j (5 strides of 32).
__device__ __forceinline__ float collapse_row(const float* __restrict__ W1,
                                              const float* __restrict__ w2reg,
                                              int r, int lane) {
    const float* row = W1 + r * HIDDEN;
    float s = 0.f;
    #pragma unroll
    for (int k = 0; k < 5; k++)
        s = fmaf(__ldg(row + lane + 32 * k), w2reg[k], s);
    #pragma unroll
    for (int o = 16; o > 0; o >>= 1)
        s += __shfl_xor_sync(0xFFFFFFFFu, s, o);
    return s;   // valid in all lanes
}

// ---------------------------------------------------------------------------
// Fused persistent kernel (4 blocks/SM). R10 structure; ONLY change vs R10:
// stage 1 manually unrolled x2 with independent load chains (2 loads in
// flight per warp instead of ~1 -> halves exposed DRAM latency there).
//   Stage 0: per-block weight collapse (W1/W2 L2-resident after wave 1).
//   Stage 1: node projections p[n] = x[n].w[0:64].
//   Stage 2 (pre-barrier, independent of p): indices + q[k] = ea.w[64:80]+c.
//   Barrier: sense-reversing grid barrier (all blocks resident by design).
//   Stage 3: 14 scattered p-gathers (L2-resident 400KB), out = sigmoid(ps+q).
// ---------------------------------------------------------------------------
__global__ __launch_bounds__(NTHREADS, 4)
void fused_kernel(const float* __restrict__ x,
                  const void*  __restrict__ ei_raw,
                  const float* __restrict__ ea,
                  const float* __restrict__ W1,
                  const float* __restrict__ b1,
                  const float* __restrict__ W2,
                  const float* __restrict__ b2,
                  float* __restrict__ out) {
    __shared__ float sw[NUM_PAR];
    __shared__ float sc;
    __shared__ int   smult;
    int t = threadIdx.x;
    int warp = t >> 5;
    int lane = t & 31;

    // ---- Stage 0: weight collapse (all 8 warps; 10 rows each) ----
    {
        float w2[5];
        #pragma unroll
        for (int k = 0; k < 5; k++) w2[k] = __ldg(W2 + lane + 32 * k);
        #pragma unroll
        for (int rr = 0; rr < 10; rr++) {
            int r = warp * 10 + rr;
            float s = collapse_row(W1, w2, r, lane);
            if (lane == 0) sw[r] = s;
        }
        if (warp == 7) {   // c = b1 . W2 + b2
            float s = 0.f;
            #pragma unroll
            for (int k = 0; k < 5; k++)
                s = fmaf(__ldg(b1 + lane + 32 * k), w2[k], s);
            #pragma unroll
            for (int o = 16; o > 0; o >>= 1)
                s += __shfl_xor_sync(0xFFFFFFFFu, s, o);
            if (lane == 0) sc = s + __ldg(b2);
        }
        if (warp == 0) {
            // Dtype probe: 32 entries as int64 all in [0,N_NODES) <=> int64
            // (int32 data would need 32 zero hi-words: P ~ 1e-160).
            const long long* ei64 = (const long long*)ei_raw;
            long long v = __ldg(ei64 + lane);
            unsigned b = __ballot_sync(0xFFFFFFFFu, v >= 0 && v < N_NODES);
            if (lane == 0) smult = (b == 0xFFFFFFFFu) ? 2 : 1;
        }
    }
    __syncthreads();

    // ---- Stage 1: node projections, manual x2 unroll (independent chains) ----
    {
        int half = lane >> 4;
        int q    = lane & 15;
        float w0 = sw[q * 4 + 0];
        float w1 = sw[q * 4 + 1];
        float w2r = sw[q * 4 + 2];
        float w3 = sw[q * 4 + 3];

        const float4* x4 = (const float4*)x;
        const int stride = NBLOCKS * 16;            // nodes per sweep
        int node = blockIdx.x * 16 + warp * 2 + half;

        for (; node + stride < N_NODES; node += 2 * stride) {
            int nodeB = node + stride;
            // Both loads issued before either reduce chain.
            float4 vA = __ldg(x4 + (size_t)node  * 16 + q);
            float4 vB = __ldg(x4 + (size_t)nodeB * 16 + q);
            float sA = fmaf(vA.x, w0, fmaf(vA.y, w1, fmaf(vA.z, w2r, vA.w * w3)));
            float sB = fmaf(vB.x, w0, fmaf(vB.y, w1, fmaf(vB.z, w2r, vB.w * w3)));
            #pragma unroll
            for (int o = 8; o > 0; o >>= 1) {
                sA += __shfl_xor_sync(0xFFFFFFFFu, sA, o);
                sB += __shfl_xor_sync(0xFFFFFFFFu, sB, o);
            }
            if (q == 0) {
                g_p[node]  = sA;
                g_p[nodeB] = sB;
            }
        }
        if (node < N_NODES) {   // tail (at most one sweep)
            float4 v = __ldg(x4 + (size_t)node * 16 + q);
            float s = fmaf(v.x, w0, fmaf(v.y, w1, fmaf(v.z, w2r, v.w * w3)));
            #pragma unroll
            for (int o = 8; o > 0; o >>= 1)
                s += __shfl_xor_sync(0xFFFFFFFFu, s, o);
            if (q == 0) g_p[node] = s;
        }
    }

    // ---- Stage 2 (pre-barrier): indices + q = ea.w + c ----
    const int mult = smult;
    const float cc = sc;
    const int* eidx = (const int*)ei_raw;   // low 4B hold the value (LE)
    const int base = blockIdx.x * (NTHREADS * EPT) + t;

    int srcs[EPT], dsts[EPT];
    #pragma unroll
    for (int k = 0; k < EPT; k++) {
        int e  = base + k * NTHREADS;
        int ec = e < N_EDGES ? e : (N_EDGES - 1);
        srcs[k] = __ldg(eidx + (size_t)mult * ec);
        dsts[k] = __ldg(eidx + (size_t)mult * ((size_t)N_EDGES + ec));
    }

    float q[EPT];
    // Pipeline ea loads one edge ahead (as in R10).
    float4 c0, c1, c2, c3;
    {
        int e = base < N_EDGES ? base : (N_EDGES - 1);
        const float4* A = (const float4*)(ea + (size_t)e * D_EDGE);
        c0 = __ldg(A + 0); c1 = __ldg(A + 1); c2 = __ldg(A + 2); c3 = __ldg(A + 3);
    }
    #pragma unroll
    for (int k = 0; k < EPT; k++) {
        float4 n0, n1, n2, n3;
        if (k + 1 < EPT) {
            int e  = base + (k + 1) * NTHREADS;
            int ec = e < N_EDGES ? e : (N_EDGES - 1);
            const float4* A = (const float4*)(ea + (size_t)ec * D_EDGE);
            n0 = __ldg(A + 0); n1 = __ldg(A + 1); n2 = __ldg(A + 2); n3 = __ldg(A + 3);
        }
        float z0 = fmaf(c0.x, sw[64], fmaf(c0.y, sw[65], fmaf(c0.z, sw[66], c0.w * sw[67])));
        float z1 = fmaf(c1.x, sw[68], fmaf(c1.y, sw[69], fmaf(c1.z, sw[70], c1.w * sw[71])));
        float z2 = fmaf(c2.x, sw[72], fmaf(c2.y, sw[73], fmaf(c2.z, sw[74], c2.w * sw[75])));
        float z3 = fmaf(c3.x, sw[76], fmaf(c3.y, sw[77], fmaf(c3.z, sw[78], c3.w * sw[79])));
        q[k] = cc + ((z0 + z1) + (z2 + z3));
        c0 = n0; c1 = n1; c2 = n2; c3 = n3;
    }

    // ---- Grid barrier (sense-reversing; all blocks resident) ----
    __syncthreads();
    if (t == 0) {
        int gen = g_flag;                    // same value in all blocks:
        __threadfence();                     // flag only moves after all arrive
        int a = atomicAdd(&g_cnt, 1);
        if (a == NBLOCKS - 1) {
            g_cnt = 0;                       // self-reset for next replay
            __threadfence();
            g_flag = gen + 1;                // release
        } else {
            while (g_flag == gen) { }        // spin (volatile)
        }
        __threadfence();
    }
    __syncthreads();

    // ---- Stage 3: scattered gathers + finish ----
    float ps[EPT];
    #pragma unroll
    for (int k = 0; k < EPT; k++)
        ps[k] = g_p[srcs[k]] + g_p[dsts[k]];

    #pragma unroll
    for (int k = 0; k < EPT; k++) {
        int e = base + k * NTHREADS;
        if (e < N_EDGES) {
            float z = ps[k] + q[k];
            out[e] = 1.0f / (1.0f + __expf(-z));
        }
    }
}

extern "C" void kernel_launch(void* const* d_in, const int* in_sizes, int n_in,
                              void* d_out, int out_size) {
    // metadata order: x, edge_index, edge_attr, W1, b1, W2, b2
    const float* x  = (const float*)d_in[0];
    const void*  ei = d_in[1];
    const float* ea = (const float*)d_in[2];
    const float* W1 = (const float*)d_in[3];
    const float* b1 = (const float*)d_in[4];
    const float* W2 = (const float*)d_in[5];
    const float* b2 = (const float*)d_in[6];
    float* out = (float*)d_out;

    fused_kernel<<<NBLOCKS, NTHREADS>>>(x, ei, ea, W1, b1, W2, b2, out);
}